// round 12
// baseline (speedup 1.0000x reference)
#include <cuda_runtime.h>
#include <math_constants.h>

#define BATCH        1048576
#define NUM_GT       8
#define LAMBDA_COORD 5.0f
#define TPB          128          // elements per block == threads per block

// corner smem stride: 8 boxes * float4 + 16B pad = 36 floats/elem.
// LDS.128 phase: bank offset 4*t mod 32 distinct across 8 consecutive lanes
// -> conflict-free.
#define CSTRIDE 36

__device__ double       g_sum = 0.0;
__device__ unsigned int g_cnt = 0;

__device__ __forceinline__ float fast_sigmoid(float x) {
    return __fdividef(1.0f, 1.0f + __expf(-x));
}

__global__ void __launch_bounds__(TPB, 8)
yolo_loss_kernel(const float* __restrict__ pred,
                 const float* __restrict__ gtb,
                 const int*   __restrict__ gtc,
                 float* __restrict__ out) {
    __shared__ float        sgc[TPB * CSTRIDE];   // 18 KB: x1,y1,x2,y2 per box
    __shared__ unsigned int scls[TPB];            // 0.5 KB: 8 classes x 4-bit nibbles

    const int    t      = threadIdx.x;
    const size_t base_e = (size_t)blockIdx.x * TPB;

    // ---- stage gt boxes: coalesced load, compute corners, store to smem ----
    {
        const float4* gg = reinterpret_cast<const float4*>(gtb) + base_e * NUM_GT;
        #pragma unroll
        for (int k = 0; k < NUM_GT; k++) {
            int idx = k * TPB + t;
            float4 g = gg[idx];               // cx, cy, w, h
            int e = idx >> 3, j = idx & 7;
            float hw = g.z * 0.5f, hh = g.w * 0.5f;
            *reinterpret_cast<float4*>(&sgc[e * CSTRIDE + j * 4]) =
                make_float4(g.x - hw, g.y - hh, g.x + hw, g.y + hh);
        }
    }
    // ---- stage gt classes: pack 4 classes per u16 half (values 0..2 fit 4 bits) ----
    {
        const int4* gc = reinterpret_cast<const int4*>(gtc) + base_e * 2;
        unsigned short* s16 = reinterpret_cast<unsigned short*>(scls);
        #pragma unroll
        for (int k = 0; k < 2; k++) {
            int idx = k * TPB + t;
            int4 v = gc[idx];
            s16[idx] = (unsigned short)((v.x & 0xF) | ((v.y & 0xF) << 4) |
                                        ((v.z & 0xF) << 8) | ((v.w & 0xF) << 12));
        }
    }
    __syncthreads();

    // ---- anchor-task passes: 3 x TPB tasks cover all (element, anchor) pairs ----
    const float4* p4 = reinterpret_cast<const float4*>(pred) + base_e * 6;
    float local = 0.0f;

    #pragma unroll
    for (int pass = 0; pass < 3; pass++) {
        unsigned int task = pass * TPB + t;     // 0..383
        unsigned int e    = task / 3u;          // block-local element (mul-hi)
        float4 box  = p4[task * 2];             // x, y, w, h
        float4 rest = p4[task * 2 + 1];         // conf, l0, l1, l2

        float px = fast_sigmoid(box.x);
        float py = fast_sigmoid(box.y);
        float pw = box.z;
        float ph = box.w;

        float px1 = px - pw * 0.5f;
        float px2 = px + pw * 0.5f;
        float py1 = py - ph * 0.5f;
        float py2 = py + ph * 0.5f;
        float parea = (px2 - px1) * (py2 - py1);    // mirror reference exactly

        const float* cbase = &sgc[e * CSTRIDE];

        // ---- division-free argmax over IoU ----
        // iou_j = num_j / den_j. Whenever any num_j > 0, pw,ph > 0 so
        // parea > 0 and ALL den_j > 0 -> cross-multiplication preserves order:
        //   num_j/den_j > num_b/den_b  <=>  num_j*den_b > num_b*den_j
        // When pw<=0 or ph<=0 every num_j == 0 -> best_j stays 0, unmatched,
        // exactly matching the reference (iou = +/-0 everywhere).
        float bnum, bden;
        int   bj = 0;
        {
            float4 c = *reinterpret_cast<const float4*>(&cbase[0]);
            float ga = (c.z - c.x) * (c.w - c.y);
            float iw = fmaxf(fminf(px2, c.z) - fmaxf(px1, c.x), 0.0f);
            float ih = fmaxf(fminf(py2, c.w) - fmaxf(py1, c.y), 0.0f);
            bnum = iw * ih;
            bden = parea + ga - bnum + 1e-6f;
        }
        #pragma unroll
        for (int j = 1; j < NUM_GT; j++) {
            float4 c = *reinterpret_cast<const float4*>(&cbase[j * 4]);
            float ga = (c.z - c.x) * (c.w - c.y);
            float iw = fmaxf(fminf(px2, c.z) - fmaxf(px1, c.x), 0.0f);
            float ih = fmaxf(fminf(py2, c.w) - fmaxf(py1, c.y), 0.0f);
            float num = iw * ih;
            float den = parea + ga - num + 1e-6f;
            if (num * bden > bnum * den) { bnum = num; bden = den; bj = j; }
        }

        // matched = best_iou > 0.5; nums==0 case must be unmatched even if den<0
        bool matched = (bnum > 0.0f) && (bnum > 0.5f * bden);

        // conf loss via softplus on raw logit:
        //   matched:  -max(log(sigmoid(c)), -100)    = min(softplus(-c), 100)
        //   else:     -max(log1p(-sigmoid(c)), -100) = min(softplus(+c), 100)
        float s  = matched ? -rest.x : rest.x;
        float sp = fmaxf(s, 0.0f) + __logf(1.0f + __expf(-fabsf(s)));
        local += fminf(sp, 100.0f);

        if (matched) {
            // matched box: dynamic index -> shared memory, reconstruct raw box
            float4 mc = *reinterpret_cast<const float4*>(&cbase[bj * 4]);
            float dx = px - (mc.x + mc.z) * 0.5f;
            float dy = py - (mc.y + mc.w) * 0.5f;
            float dw = pw - (mc.z - mc.x);
            float dh = ph - (mc.w - mc.y);
            float coord = dx * dx + dy * dy + dw * dw + dh * dh;

            // class NLL: logsumexp - logit[class]
            int kc = (int)((scls[e] >> (bj * 4)) & 0xFu);
            float l0 = rest.y, l1 = rest.z, l2 = rest.w;
            float m   = fmaxf(l0, fmaxf(l1, l2));
            float lse = m + __logf(__expf(l0 - m) + __expf(l1 - m) + __expf(l2 - m));
            float lk  = (kc == 0) ? l0 : ((kc == 1) ? l1 : l2);

            local += LAMBDA_COORD * coord + (lse - lk);
        }
    }

    // ---- reduction: warp shuffle -> block -> one double atomic per block ----
    #pragma unroll
    for (int off = 16; off > 0; off >>= 1)
        local += __shfl_down_sync(0xFFFFFFFFu, local, off);

    __shared__ float warp_sums[TPB / 32];
    int lane = t & 31;
    int wid  = t >> 5;
    if (lane == 0) warp_sums[wid] = local;
    __syncthreads();

    if (t == 0) {
        float v = 0.0f;
        #pragma unroll
        for (int w = 0; w < TPB / 32; w++) v += warp_sums[w];
        atomicAdd(&g_sum, (double)v);

        __threadfence();
        unsigned int done = atomicAdd(&g_cnt, 1u);
        if (done == gridDim.x - 1) {
            out[0] = (float)(g_sum / (double)BATCH);
            g_sum = 0.0;    // reset for next graph replay
            g_cnt = 0u;
        }
    }
}

extern "C" void kernel_launch(void* const* d_in, const int* in_sizes, int n_in,
                              void* d_out, int out_size) {
    const float* pred = (const float*)d_in[0];   // (B, 3, 8) f32
    const float* gtb  = (const float*)d_in[1];   // (B, 8, 4) f32
    const int*   gtc  = (const int*)d_in[2];     // (B, 8) i32
    float* out = (float*)d_out;

    yolo_loss_kernel<<<BATCH / TPB, TPB>>>(pred, gtb, gtc, out);
}

// round 13
// speedup vs baseline: 1.0039x; 1.0039x over previous
#include <cuda_runtime.h>
#include <math_constants.h>

#define BATCH        1048576
#define NUM_GT       8
#define LAMBDA_COORD 5.0f
#define TPB          128          // elements per block == threads per block

// corner smem stride: 8 boxes * float4 + 16B pad = 36 floats/elem.
// LDS.128 phase: bank offset 4*t mod 32 distinct across 8 consecutive lanes
// -> conflict-free.
#define CSTRIDE 36

__device__ double       g_sum = 0.0;
__device__ unsigned int g_cnt = 0;

__device__ __forceinline__ float fast_sigmoid(float x) {
    return __fdividef(1.0f, 1.0f + __expf(-x));
}

__global__ void __launch_bounds__(TPB, 8)
yolo_loss_kernel(const float* __restrict__ pred,
                 const float* __restrict__ gtb,
                 const int*   __restrict__ gtc,
                 float* __restrict__ out) {
    __shared__ float        sgc[TPB * CSTRIDE];   // 18 KB: x1,y1,x2,y2 per box
    __shared__ unsigned int scls[TPB];            // 0.5 KB: 8 classes x 4-bit nibbles

    const int    t      = threadIdx.x;
    const size_t base_e = (size_t)blockIdx.x * TPB;

    // ---- stage gt boxes: coalesced load, compute corners, store to smem ----
    {
        const float4* gg = reinterpret_cast<const float4*>(gtb) + base_e * NUM_GT;
        #pragma unroll
        for (int k = 0; k < NUM_GT; k++) {
            int idx = k * TPB + t;
            float4 g = gg[idx];               // cx, cy, w, h
            int e = idx >> 3, j = idx & 7;
            float hw = g.z * 0.5f, hh = g.w * 0.5f;
            *reinterpret_cast<float4*>(&sgc[e * CSTRIDE + j * 4]) =
                make_float4(g.x - hw, g.y - hh, g.x + hw, g.y + hh);
        }
    }
    // ---- stage gt classes: pack 4 classes per u16 half (values 0..2 fit 4 bits) ----
    {
        const int4* gc = reinterpret_cast<const int4*>(gtc) + base_e * 2;
        unsigned short* s16 = reinterpret_cast<unsigned short*>(scls);
        #pragma unroll
        for (int k = 0; k < 2; k++) {
            int idx = k * TPB + t;
            int4 v = gc[idx];
            s16[idx] = (unsigned short)((v.x & 0xF) | ((v.y & 0xF) << 4) |
                                        ((v.z & 0xF) << 8) | ((v.w & 0xF) << 12));
        }
    }
    __syncthreads();

    // ---- anchor-task passes: 3 x TPB tasks cover all (element, anchor) pairs ----
    const float4* p4 = reinterpret_cast<const float4*>(pred) + base_e * 6;
    float local = 0.0f;

    #pragma unroll
    for (int pass = 0; pass < 3; pass++) {
        unsigned int task = pass * TPB + t;     // 0..383
        unsigned int e    = task / 3u;          // block-local element (mul-hi)
        float4 box  = p4[task * 2];             // x, y, w, h
        float4 rest = p4[task * 2 + 1];         // conf, l0, l1, l2

        float px = fast_sigmoid(box.x);
        float py = fast_sigmoid(box.y);
        float pw = box.z;
        float ph = box.w;

        float px1 = px - pw * 0.5f;
        float px2 = px + pw * 0.5f;
        float py1 = py - ph * 0.5f;
        float py2 = py + ph * 0.5f;
        float parea = (px2 - px1) * (py2 - py1);    // mirror reference exactly

        const float* cbase = &sgc[e * CSTRIDE];

        // ---- division-free argmax over IoU ----
        // iou_j = num_j / den_j. Whenever any num_j > 0, pw,ph > 0 so
        // parea > 0 and ALL den_j > 0 -> cross-multiplication preserves order:
        //   num_j/den_j > num_b/den_b  <=>  num_j*den_b > num_b*den_j
        // When pw<=0 or ph<=0 every num_j == 0 -> best_j stays 0, unmatched,
        // exactly matching the reference (iou = +/-0 everywhere).
        float bnum, bden;
        int   bj = 0;
        {
            float4 c = *reinterpret_cast<const float4*>(&cbase[0]);
            float ga = (c.z - c.x) * (c.w - c.y);
            float iw = fmaxf(fminf(px2, c.z) - fmaxf(px1, c.x), 0.0f);
            float ih = fmaxf(fminf(py2, c.w) - fmaxf(py1, c.y), 0.0f);
            bnum = iw * ih;
            bden = parea + ga - bnum + 1e-6f;
        }
        #pragma unroll
        for (int j = 1; j < NUM_GT; j++) {
            float4 c = *reinterpret_cast<const float4*>(&cbase[j * 4]);
            float ga = (c.z - c.x) * (c.w - c.y);
            float iw = fmaxf(fminf(px2, c.z) - fmaxf(px1, c.x), 0.0f);
            float ih = fmaxf(fminf(py2, c.w) - fmaxf(py1, c.y), 0.0f);
            float num = iw * ih;
            float den = parea + ga - num + 1e-6f;
            if (num * bden > bnum * den) { bnum = num; bden = den; bj = j; }
        }

        // matched = best_iou > 0.5; nums==0 case must be unmatched even if den<0
        bool matched = (bnum > 0.0f) && (bnum > 0.5f * bden);

        // conf loss via softplus on raw logit:
        //   matched:  -max(log(sigmoid(c)), -100)    = min(softplus(-c), 100)
        //   else:     -max(log1p(-sigmoid(c)), -100) = min(softplus(+c), 100)
        float s  = matched ? -rest.x : rest.x;
        float sp = fmaxf(s, 0.0f) + __logf(1.0f + __expf(-fabsf(s)));
        local += fminf(sp, 100.0f);

        if (matched) {
            // matched box: dynamic index -> shared memory, reconstruct raw box
            float4 mc = *reinterpret_cast<const float4*>(&cbase[bj * 4]);
            float dx = px - (mc.x + mc.z) * 0.5f;
            float dy = py - (mc.y + mc.w) * 0.5f;
            float dw = pw - (mc.z - mc.x);
            float dh = ph - (mc.w - mc.y);
            float coord = dx * dx + dy * dy + dw * dw + dh * dh;

            // class NLL: logsumexp - logit[class]
            int kc = (int)((scls[e] >> (bj * 4)) & 0xFu);
            float l0 = rest.y, l1 = rest.z, l2 = rest.w;
            float m   = fmaxf(l0, fmaxf(l1, l2));
            float lse = m + __logf(__expf(l0 - m) + __expf(l1 - m) + __expf(l2 - m));
            float lk  = (kc == 0) ? l0 : ((kc == 1) ? l1 : l2);

            local += LAMBDA_COORD * coord + (lse - lk);
        }
    }

    // ---- reduction: warp shuffle -> block -> one double atomic per block ----
    #pragma unroll
    for (int off = 16; off > 0; off >>= 1)
        local += __shfl_down_sync(0xFFFFFFFFu, local, off);

    __shared__ float warp_sums[TPB / 32];
    int lane = t & 31;
    int wid  = t >> 5;
    if (lane == 0) warp_sums[wid] = local;
    __syncthreads();

    if (t == 0) {
        float v = 0.0f;
        #pragma unroll
        for (int w = 0; w < TPB / 32; w++) v += warp_sums[w];
        atomicAdd(&g_sum, (double)v);

        __threadfence();
        unsigned int done = atomicAdd(&g_cnt, 1u);
        if (done == gridDim.x - 1) {
            out[0] = (float)(g_sum / (double)BATCH);
            g_sum = 0.0;    // reset for next graph replay
            g_cnt = 0u;
        }
    }
}

extern "C" void kernel_launch(void* const* d_in, const int* in_sizes, int n_in,
                              void* d_out, int out_size) {
    const float* pred = (const float*)d_in[0];   // (B, 3, 8) f32
    const float* gtb  = (const float*)d_in[1];   // (B, 8, 4) f32
    const int*   gtc  = (const int*)d_in[2];     // (B, 8) i32
    float* out = (float*)d_out;

    yolo_loss_kernel<<<BATCH / TPB, TPB>>>(pred, gtb, gtc, out);
}